// round 4
// baseline (speedup 1.0000x reference)
#include <cuda_runtime.h>
#include <math.h>

#define NN 100000
#define CC 128
#define EE 600000
#define EPSV 1e-10f

#define RT 64                          // rows per GEMM tile
#define NTILES ((NN + RT - 1) / RT)    // 1563
#define GBLK 148                       // persistent blocks (1/SM)
#define THREADS 384                    // 8 compute warps + 4 producer warps

#define SCAN_B 1024
#define SCAN_NBLK ((NN + SCAN_B - 1) / SCAN_B)   // 98

typedef unsigned long long u64;
typedef unsigned int u32;

// ---------------------------------------------------------------------------
// Device scratch (no allocation allowed in kernel_launch). NOTE: no g_ptr —
// the segment-sum never touches global memory anymore.
// ---------------------------------------------------------------------------
__device__ int g_cnt[NN];                // per-node edge count (self-cleaned)
__device__ int g_scan[NN];               // block-inclusive scan of counts
__device__ int g_rowstart[NN];           // CSR row start (exclusive scan)
__device__ int g_cursor[NN];             // write cursor for permutation
__device__ int g_bsums[SCAN_NBLK];       // per-scan-block totals
__device__ u64 g_edges[EE];              // packed (norm:f32 << 32 | src:u32)

// ---------------------------------------------------------------------------
// packed f32x2 helpers (sm_100+; ptxas never emits FFMA2 from C++)
// ---------------------------------------------------------------------------
__device__ __forceinline__ u64 ffma2(u64 a, u64 b, u64 c) {
    u64 d;
    asm("fma.rn.f32x2 %0, %1, %2, %3;" : "=l"(d) : "l"(a), "l"(b), "l"(c));
    return d;
}
__device__ __forceinline__ u64 pack2(float lo, float hi) {
    u64 d;
    asm("mov.b64 %0, {%1, %2};" : "=l"(d) : "f"(lo), "f"(hi));
    return d;
}
__device__ __forceinline__ void unpack2(u64 d, float& lo, float& hi) {
    asm("mov.b64 {%0, %1}, %2;" : "=f"(lo), "=f"(hi) : "l"(d));
}

// ---------------------------------------------------------------------------
// CSR build: histogram -> scan(x3) -> permute  (counts pre-zeroed: BSS on
// first call, self-cleaned by the fused kernel on every call)
// ---------------------------------------------------------------------------
__global__ void hist_kernel(const int* __restrict__ ei) {
    const int e = blockIdx.x * blockDim.x + threadIdx.x;
    if (e < EE) atomicAdd(&g_cnt[__ldg(ei + EE + e)], 1);
}

__global__ __launch_bounds__(SCAN_B)
void scan_block_kernel() {
    __shared__ int wsum[32];
    const int tid  = threadIdx.x;
    const int gi   = blockIdx.x * SCAN_B + tid;
    const int lane = tid & 31;
    const int wid  = tid >> 5;

    int v = (gi < NN) ? g_cnt[gi] : 0;
    int s = v;
#pragma unroll
    for (int d = 1; d < 32; d <<= 1) {
        int t = __shfl_up_sync(0xffffffffu, s, d);
        if (lane >= d) s += t;
    }
    if (lane == 31) wsum[wid] = s;
    __syncthreads();
    if (wid == 0) {
        int w = wsum[lane];
        int ws = w;
#pragma unroll
        for (int d = 1; d < 32; d <<= 1) {
            int t = __shfl_up_sync(0xffffffffu, ws, d);
            if (lane >= d) ws += t;
        }
        wsum[lane] = ws - w;
    }
    __syncthreads();
    const int incl = s + wsum[wid];
    if (gi < NN) g_scan[gi] = incl;
    if (tid == SCAN_B - 1) g_bsums[blockIdx.x] = incl;
}

// parallel warp scan over the 98 block sums (was a serial 8.3us loop)
__global__ void scan_sums_kernel() {
    const int lane = threadIdx.x & 31;
    const int base = lane * 4;
    int v[4];
    int tot = 0;
#pragma unroll
    for (int j = 0; j < 4; j++) {
        const int idx = base + j;
        v[j] = (idx < SCAN_NBLK) ? g_bsums[idx] : 0;
        tot += v[j];
    }
    int s = tot;
#pragma unroll
    for (int d = 1; d < 32; d <<= 1) {
        int t = __shfl_up_sync(0xffffffffu, s, d);
        if (lane >= d) s += t;
    }
    int run = s - tot;   // exclusive prefix of this lane's chunk
#pragma unroll
    for (int j = 0; j < 4; j++) {
        const int idx = base + j;
        if (idx < SCAN_NBLK) g_bsums[idx] = run;
        run += v[j];
    }
}

__global__ void finalize_scan_kernel() {
    const int i = blockIdx.x * blockDim.x + threadIdx.x;
    if (i < NN) {
        const int rs = g_scan[i] - g_cnt[i] + g_bsums[i / SCAN_B];
        g_rowstart[i] = rs;
        g_cursor[i]   = rs;
    }
}

__global__ void permute_kernel(const int* __restrict__ ei,
                               const float* __restrict__ en) {
    const int e = blockIdx.x * blockDim.x + threadIdx.x;
    if (e >= EE) return;
    const int   s = __ldg(ei + e);
    const int   t = __ldg(ei + EE + e);
    const float n = __ldg(en + e);
    const int   p = atomicAdd(&g_cursor[t], 1);
    g_edges[p] = ((u64)__float_as_uint(n) << 32) | (u32)s;
}

// ---------------------------------------------------------------------------
// FUSED kernel: producer warps aggregate CSR edges for tile t+GBLK into smem
// (double-buffered) while compute warps run the FFMA2 dual-GEMM on tile t.
//   out[0:N)  = ptr @ loc_w.T + loc_b
//   out[N:2N) = softplus(ptr @ std_w.T + std_b) + EPS
// smem: wt (f32x2 weight pairs) 128KB | pt[2] fp32 row tiles 2x32KB | bias 1KB
// ---------------------------------------------------------------------------
__device__ __forceinline__ void fill_tile(float* __restrict__ ptbuf, int tile,
                                          const float* __restrict__ emb,
                                          int gwid, int lane) {
    const int rbase = tile * RT + gwid * 16;
#pragma unroll 1
    for (int r = 0; r < 16; r++) {
        const int row = rbase + r;
        float4 a = make_float4(0.f, 0.f, 0.f, 0.f);
        if (row < NN) {
            const int beg = __ldg(&g_rowstart[row]);
            const int cnt = __ldg(&g_cnt[row]);
            int i = 0;
            for (; i + 1 < cnt; i += 2) {
                const u64 r0 = __ldg(&g_edges[beg + i]);
                const u64 r1 = __ldg(&g_edges[beg + i + 1]);
                const float4 v0 = *reinterpret_cast<const float4*>(
                    emb + (size_t)(u32)r0 * CC + lane * 4);
                const float4 v1 = *reinterpret_cast<const float4*>(
                    emb + (size_t)(u32)r1 * CC + lane * 4);
                const float n0 = __uint_as_float((u32)(r0 >> 32));
                const float n1 = __uint_as_float((u32)(r1 >> 32));
                a.x += v0.x * n0; a.y += v0.y * n0;
                a.z += v0.z * n0; a.w += v0.w * n0;
                a.x += v1.x * n1; a.y += v1.y * n1;
                a.z += v1.z * n1; a.w += v1.w * n1;
            }
            if (i < cnt) {
                const u64 r0 = __ldg(&g_edges[beg + i]);
                const float4 v0 = *reinterpret_cast<const float4*>(
                    emb + (size_t)(u32)r0 * CC + lane * 4);
                const float n0 = __uint_as_float((u32)(r0 >> 32));
                a.x += v0.x * n0; a.y += v0.y * n0;
                a.z += v0.z * n0; a.w += v0.w * n0;
            }
            if (lane == 0) g_cnt[row] = 0;   // self-clean for next invocation
        }
        *reinterpret_cast<float4*>(ptbuf + (gwid * 16 + r) * CC + lane * 4) = a;
    }
}

__global__ __launch_bounds__(THREADS, 1)
void fused_kernel(const float* __restrict__ emb,
                  const float* __restrict__ lw, const float* __restrict__ lb,
                  const float* __restrict__ sw, const float* __restrict__ sb,
                  float* __restrict__ out) {
    extern __shared__ char smem_raw[];
    u64*   wt    = reinterpret_cast<u64*>(smem_raw);       // CC*CC pairs
    float* pt0   = reinterpret_cast<float*>(wt + CC * CC); // RT*CC
    float* pt1   = pt0 + RT * CC;                          // RT*CC
    u64*   sbias = reinterpret_cast<u64*>(pt1 + RT * CC);  // CC pairs

    const int tid  = threadIdx.x;
    const int wid  = tid >> 5;
    const int lane = tid & 31;

    // ---- cooperative weight/bias load (all 384 threads) ----
    for (int idx = tid; idx < CC * CC; idx += THREADS) {
        const int pid = idx >> 7;
        const int k   = idx & (CC - 1);
        const int jc0 = pid * 2;
        float a, b;
        if (jc0 < CC) { a = lw[jc0 * CC + k];        b = lw[(jc0 + 1) * CC + k]; }
        else          { a = sw[(jc0 - CC) * CC + k]; b = sw[(jc0 + 1 - CC) * CC + k]; }
        wt[k * CC + pid] = pack2(a, b);
    }
    if (tid < CC) {
        const int jc0 = tid * 2;
        float a, b;
        if (jc0 < CC) { a = lb[jc0];      b = lb[jc0 + 1]; }
        else          { a = sb[jc0 - CC]; b = sb[jc0 + 1 - CC]; }
        sbias[tid] = pack2(a, b);
    }

    // ---- prologue: producers fill buffer 0 with this block's first tile ----
    if (wid >= 8) fill_tile(pt0, blockIdx.x, emb, wid - 8, lane);
    __syncthreads();

    const int c  = lane;       // weight pair lane
    const int rg = wid;        // compute row group (wid < 8)

    int buf = 0;
    for (int t = blockIdx.x; t < NTILES; t += GBLK) {
        float* cur = buf ? pt1 : pt0;
        float* nxt = buf ? pt0 : pt1;

        if (wid >= 8) {
            // ---- producer warps: aggregate next tile ----
            const int t2 = t + GBLK;
            if (t2 < NTILES) fill_tile(nxt, t2, emb, wid - 8, lane);
        } else {
            // ---- compute warps: dual GEMM on current tile ----
            const int row0 = t * RT;
            u64 acc[8][4];
#pragma unroll
            for (int r = 0; r < 8; r++)
#pragma unroll
                for (int p = 0; p < 4; p++) acc[r][p] = 0ull;

#pragma unroll 4
            for (int k = 0; k < CC; k++) {
                const u64 w0 = wt[k * CC +  0 + c];
                const u64 w1 = wt[k * CC + 32 + c];
                const u64 w2 = wt[k * CC + 64 + c];
                const u64 w3 = wt[k * CC + 96 + c];
#pragma unroll
                for (int r = 0; r < 8; r++) {
                    const float v = cur[(rg * 8 + r) * CC + k];  // broadcast
                    const u64 rv = pack2(v, v);
                    acc[r][0] = ffma2(rv, w0, acc[r][0]);
                    acc[r][1] = ffma2(rv, w1, acc[r][1]);
                    acc[r][2] = ffma2(rv, w2, acc[r][2]);
                    acc[r][3] = ffma2(rv, w3, acc[r][3]);
                }
            }

            // ---- epilogue: bias (+softplus for std half), float2 stores ----
#pragma unroll
            for (int p = 0; p < 4; p++) {
                const int pid = p * 32 + c;
                const int jc0 = pid * 2;
                float b0, b1;
                unpack2(sbias[pid], b0, b1);
                const bool is_std = (jc0 >= CC);
#pragma unroll
                for (int r = 0; r < 8; r++) {
                    const int row = row0 + rg * 8 + r;
                    if (row >= NN) break;
                    float x0, x1;
                    unpack2(acc[r][p], x0, x1);
                    x0 += b0; x1 += b1;
                    float* dst;
                    if (is_std) {
                        x0 = ((x0 > 0.f) ? (x0 + log1pf(__expf(-x0)))
                                         : log1pf(__expf(x0))) + EPSV;
                        x1 = ((x1 > 0.f) ? (x1 + log1pf(__expf(-x1)))
                                         : log1pf(__expf(x1))) + EPSV;
                        dst = out + (size_t)NN * CC + (size_t)row * CC + (jc0 - CC);
                    } else {
                        dst = out + (size_t)row * CC + jc0;
                    }
                    *reinterpret_cast<float2*>(dst) = make_float2(x0, x1);
                }
            }
        }
        __syncthreads();
        buf ^= 1;
    }
}

// ---------------------------------------------------------------------------
// Launch. Inputs: emb, loc_w, loc_b, std_w, std_b, edge_index, edge_norm
// ---------------------------------------------------------------------------
extern "C" void kernel_launch(void* const* d_in, const int* in_sizes, int n_in,
                              void* d_out, int out_size) {
    const float* emb = (const float*)d_in[0];
    const float* lw  = (const float*)d_in[1];
    const float* lb  = (const float*)d_in[2];
    const float* sw  = (const float*)d_in[3];
    const float* sb  = (const float*)d_in[4];
    const int*   ei  = (const int*)  d_in[5];
    const float* en  = (const float*)d_in[6];
    float* out = (float*)d_out;

    hist_kernel<<<(EE + 255) / 256, 256>>>(ei);
    scan_block_kernel<<<SCAN_NBLK, SCAN_B>>>();
    scan_sums_kernel<<<1, 32>>>();
    finalize_scan_kernel<<<(NN + 255) / 256, 256>>>();
    permute_kernel<<<(EE + 255) / 256, 256>>>(ei, en);

    const int smem_bytes = (CC * CC + CC) * (int)sizeof(u64)
                         + 2 * RT * CC * (int)sizeof(float);   // 197,632 B
    static int smem_set = 0;
    if (!smem_set) {
        cudaFuncSetAttribute(fused_kernel,
                             cudaFuncAttributeMaxDynamicSharedMemorySize, smem_bytes);
        smem_set = 1;
    }
    fused_kernel<<<GBLK, THREADS, smem_bytes>>>(emb, lw, lb, sw, sb, out);
}

// round 5
// speedup vs baseline: 1.4192x; 1.4192x over previous
#include <cuda_runtime.h>
#include <math.h>

#define NN 100000
#define CC 128
#define EE 600000
#define EPSV 1e-10f

#define RT 64                          // rows per GEMM tile
#define NTILES ((NN + RT - 1) / RT)    // 1563
#define GBLK 148                       // persistent blocks (1/SM)
#define THREADS 512                    // 8 compute warps + 8 producer warps

#define SCAN_B 1024
#define SCAN_NBLK ((NN + SCAN_B - 1) / SCAN_B)   // 98

typedef unsigned long long u64;
typedef unsigned int u32;

// ---------------------------------------------------------------------------
// Device scratch. No g_ptr — aggregation lives in smem only.
// ---------------------------------------------------------------------------
__device__ int g_cnt[NN];                // per-node edge count (self-cleaned)
__device__ int g_scan[NN];               // block-inclusive scan of counts
__device__ int g_rowstart[NN];           // CSR row start (exclusive scan)
__device__ int g_cursor[NN];             // write cursor for permutation
__device__ int g_bsums[SCAN_NBLK];       // per-scan-block totals
__device__ u64 g_edges[EE];              // packed (norm:f32 << 32 | src:u32)

// ---------------------------------------------------------------------------
// packed f32x2 helpers (sm_100+; ptxas never emits FFMA2 from C++)
// ---------------------------------------------------------------------------
__device__ __forceinline__ u64 ffma2(u64 a, u64 b, u64 c) {
    u64 d;
    asm("fma.rn.f32x2 %0, %1, %2, %3;" : "=l"(d) : "l"(a), "l"(b), "l"(c));
    return d;
}
__device__ __forceinline__ u64 pack2(float lo, float hi) {
    u64 d;
    asm("mov.b64 %0, {%1, %2};" : "=l"(d) : "f"(lo), "f"(hi));
    return d;
}
__device__ __forceinline__ void unpack2(u64 d, float& lo, float& hi) {
    asm("mov.b64 {%0, %1}, %2;" : "=f"(lo), "=f"(hi) : "l"(d));
}

// ---------------------------------------------------------------------------
// CSR build: histogram -> scan(x3) -> permute
// ---------------------------------------------------------------------------
__global__ void hist_kernel(const int* __restrict__ ei) {
    const int e = blockIdx.x * blockDim.x + threadIdx.x;
    if (e < EE) atomicAdd(&g_cnt[__ldg(ei + EE + e)], 1);
}

__global__ __launch_bounds__(SCAN_B)
void scan_block_kernel() {
    __shared__ int wsum[32];
    const int tid  = threadIdx.x;
    const int gi   = blockIdx.x * SCAN_B + tid;
    const int lane = tid & 31;
    const int wid  = tid >> 5;

    int v = (gi < NN) ? g_cnt[gi] : 0;
    int s = v;
#pragma unroll
    for (int d = 1; d < 32; d <<= 1) {
        int t = __shfl_up_sync(0xffffffffu, s, d);
        if (lane >= d) s += t;
    }
    if (lane == 31) wsum[wid] = s;
    __syncthreads();
    if (wid == 0) {
        int w = wsum[lane];
        int ws = w;
#pragma unroll
        for (int d = 1; d < 32; d <<= 1) {
            int t = __shfl_up_sync(0xffffffffu, ws, d);
            if (lane >= d) ws += t;
        }
        wsum[lane] = ws - w;
    }
    __syncthreads();
    const int incl = s + wsum[wid];
    if (gi < NN) g_scan[gi] = incl;
    if (tid == SCAN_B - 1) g_bsums[blockIdx.x] = incl;
}

__global__ void scan_sums_kernel() {
    const int lane = threadIdx.x & 31;
    const int base = lane * 4;
    int v[4];
    int tot = 0;
#pragma unroll
    for (int j = 0; j < 4; j++) {
        const int idx = base + j;
        v[j] = (idx < SCAN_NBLK) ? g_bsums[idx] : 0;
        tot += v[j];
    }
    int s = tot;
#pragma unroll
    for (int d = 1; d < 32; d <<= 1) {
        int t = __shfl_up_sync(0xffffffffu, s, d);
        if (lane >= d) s += t;
    }
    int run = s - tot;
#pragma unroll
    for (int j = 0; j < 4; j++) {
        const int idx = base + j;
        if (idx < SCAN_NBLK) g_bsums[idx] = run;
        run += v[j];
    }
}

__global__ void finalize_scan_kernel() {
    const int i = blockIdx.x * blockDim.x + threadIdx.x;
    if (i < NN) {
        const int rs = g_scan[i] - g_cnt[i] + g_bsums[i / SCAN_B];
        g_rowstart[i] = rs;
        g_cursor[i]   = rs;
    }
}

__global__ void permute_kernel(const int* __restrict__ ei,
                               const float* __restrict__ en) {
    const int e = blockIdx.x * blockDim.x + threadIdx.x;
    if (e >= EE) return;
    const int   s = __ldg(ei + e);
    const int   t = __ldg(ei + EE + e);
    const float n = __ldg(en + e);
    const int   p = atomicAdd(&g_cursor[t], 1);
    g_edges[p] = ((u64)__float_as_uint(n) << 32) | (u32)s;
}

// ---------------------------------------------------------------------------
// Producer tile fill: 8 warps, each handles 8 rows. 4-deep edge unroll for
// MLP (~16 cache lines in flight per warp).
// ---------------------------------------------------------------------------
__device__ __forceinline__ void fill_tile(float* __restrict__ ptbuf, int tile,
                                          const float* __restrict__ emb,
                                          int gwid, int lane) {
    const int rbase = tile * RT + gwid * 8;
#pragma unroll 1
    for (int r = 0; r < 8; r++) {
        const int row = rbase + r;
        float4 a = make_float4(0.f, 0.f, 0.f, 0.f);
        if (row < NN) {
            const int beg = __ldg(&g_rowstart[row]);
            const int cnt = __ldg(&g_cnt[row]);
            int i = 0;
            for (; i + 3 < cnt; i += 4) {
                const u64 r0 = __ldg(&g_edges[beg + i]);
                const u64 r1 = __ldg(&g_edges[beg + i + 1]);
                const u64 r2 = __ldg(&g_edges[beg + i + 2]);
                const u64 r3 = __ldg(&g_edges[beg + i + 3]);
                const float4 v0 = *reinterpret_cast<const float4*>(
                    emb + (size_t)(u32)r0 * CC + lane * 4);
                const float4 v1 = *reinterpret_cast<const float4*>(
                    emb + (size_t)(u32)r1 * CC + lane * 4);
                const float4 v2 = *reinterpret_cast<const float4*>(
                    emb + (size_t)(u32)r2 * CC + lane * 4);
                const float4 v3 = *reinterpret_cast<const float4*>(
                    emb + (size_t)(u32)r3 * CC + lane * 4);
                const float n0 = __uint_as_float((u32)(r0 >> 32));
                const float n1 = __uint_as_float((u32)(r1 >> 32));
                const float n2 = __uint_as_float((u32)(r2 >> 32));
                const float n3 = __uint_as_float((u32)(r3 >> 32));
                a.x += v0.x * n0; a.y += v0.y * n0; a.z += v0.z * n0; a.w += v0.w * n0;
                a.x += v1.x * n1; a.y += v1.y * n1; a.z += v1.z * n1; a.w += v1.w * n1;
                a.x += v2.x * n2; a.y += v2.y * n2; a.z += v2.z * n2; a.w += v2.w * n2;
                a.x += v3.x * n3; a.y += v3.y * n3; a.z += v3.z * n3; a.w += v3.w * n3;
            }
            for (; i < cnt; i++) {
                const u64 r0 = __ldg(&g_edges[beg + i]);
                const float4 v0 = *reinterpret_cast<const float4*>(
                    emb + (size_t)(u32)r0 * CC + lane * 4);
                const float n0 = __uint_as_float((u32)(r0 >> 32));
                a.x += v0.x * n0; a.y += v0.y * n0; a.z += v0.z * n0; a.w += v0.w * n0;
            }
            if (lane == 0) g_cnt[row] = 0;   // self-clean for next invocation
        }
        *reinterpret_cast<float4*>(ptbuf + (gwid * 8 + r) * CC + lane * 4) = a;
    }
}

// ---------------------------------------------------------------------------
// FUSED kernel: 8 producer warps aggregate tile t+GBLK into smem (double-
// buffered) while 8 compute warps run the FFMA2 dual-GEMM on tile t.
// ---------------------------------------------------------------------------
__global__ __launch_bounds__(THREADS, 1)
void fused_kernel(const float* __restrict__ emb,
                  const float* __restrict__ lw, const float* __restrict__ lb,
                  const float* __restrict__ sw, const float* __restrict__ sb,
                  float* __restrict__ out) {
    extern __shared__ char smem_raw[];
    u64*   wt    = reinterpret_cast<u64*>(smem_raw);       // CC*CC pairs
    float* pt0   = reinterpret_cast<float*>(wt + CC * CC); // RT*CC
    float* pt1   = pt0 + RT * CC;                          // RT*CC
    u64*   sbias = reinterpret_cast<u64*>(pt1 + RT * CC);  // CC pairs

    const int tid  = threadIdx.x;
    const int wid  = tid >> 5;
    const int lane = tid & 31;

    // ---- cooperative weight/bias load ----
    for (int idx = tid; idx < CC * CC; idx += THREADS) {
        const int pid = idx >> 7;
        const int k   = idx & (CC - 1);
        const int jc0 = pid * 2;
        float a, b;
        if (jc0 < CC) { a = lw[jc0 * CC + k];        b = lw[(jc0 + 1) * CC + k]; }
        else          { a = sw[(jc0 - CC) * CC + k]; b = sw[(jc0 + 1 - CC) * CC + k]; }
        wt[k * CC + pid] = pack2(a, b);
    }
    if (tid < CC) {
        const int jc0 = tid * 2;
        float a, b;
        if (jc0 < CC) { a = lb[jc0];      b = lb[jc0 + 1]; }
        else          { a = sb[jc0 - CC]; b = sb[jc0 + 1 - CC]; }
        sbias[tid] = pack2(a, b);
    }

    // ---- prologue: producers fill buffer 0 with this block's first tile ----
    if (wid >= 8) fill_tile(pt0, blockIdx.x, emb, wid - 8, lane);
    __syncthreads();

    const int c  = lane;
    const int rg = wid;        // compute row group (wid < 8)

    int buf = 0;
    for (int t = blockIdx.x; t < NTILES; t += GBLK) {
        float* cur = buf ? pt1 : pt0;
        float* nxt = buf ? pt0 : pt1;

        if (wid >= 8) {
            const int t2 = t + GBLK;
            if (t2 < NTILES) fill_tile(nxt, t2, emb, wid - 8, lane);
        } else {
            const int row0 = t * RT;
            u64 acc[8][4];
#pragma unroll
            for (int r = 0; r < 8; r++)
#pragma unroll
                for (int p = 0; p < 4; p++) acc[r][p] = 0ull;

#pragma unroll 4
            for (int k = 0; k < CC; k++) {
                const u64 w0 = wt[k * CC +  0 + c];
                const u64 w1 = wt[k * CC + 32 + c];
                const u64 w2 = wt[k * CC + 64 + c];
                const u64 w3 = wt[k * CC + 96 + c];
#pragma unroll
                for (int r = 0; r < 8; r++) {
                    const float v = cur[(rg * 8 + r) * CC + k];  // broadcast
                    const u64 rv = pack2(v, v);
                    acc[r][0] = ffma2(rv, w0, acc[r][0]);
                    acc[r][1] = ffma2(rv, w1, acc[r][1]);
                    acc[r][2] = ffma2(rv, w2, acc[r][2]);
                    acc[r][3] = ffma2(rv, w3, acc[r][3]);
                }
            }

#pragma unroll
            for (int p = 0; p < 4; p++) {
                const int pid = p * 32 + c;
                const int jc0 = pid * 2;
                float b0, b1;
                unpack2(sbias[pid], b0, b1);
                const bool is_std = (jc0 >= CC);
#pragma unroll
                for (int r = 0; r < 8; r++) {
                    const int row = row0 + rg * 8 + r;
                    if (row >= NN) break;
                    float x0, x1;
                    unpack2(acc[r][p], x0, x1);
                    x0 += b0; x1 += b1;
                    float* dst;
                    if (is_std) {
                        x0 = ((x0 > 0.f) ? (x0 + log1pf(__expf(-x0)))
                                         : log1pf(__expf(x0))) + EPSV;
                        x1 = ((x1 > 0.f) ? (x1 + log1pf(__expf(-x1)))
                                         : log1pf(__expf(x1))) + EPSV;
                        dst = out + (size_t)NN * CC + (size_t)row * CC + (jc0 - CC);
                    } else {
                        dst = out + (size_t)row * CC + jc0;
                    }
                    *reinterpret_cast<float2*>(dst) = make_float2(x0, x1);
                }
            }
        }
        __syncthreads();
        buf ^= 1;
    }
}

// ---------------------------------------------------------------------------
// Launch. Inputs: emb, loc_w, loc_b, std_w, std_b, edge_index, edge_norm
// ---------------------------------------------------------------------------
extern "C" void kernel_launch(void* const* d_in, const int* in_sizes, int n_in,
                              void* d_out, int out_size) {
    const float* emb = (const float*)d_in[0];
    const float* lw  = (const float*)d_in[1];
    const float* lb  = (const float*)d_in[2];
    const float* sw  = (const float*)d_in[3];
    const float* sb  = (const float*)d_in[4];
    const int*   ei  = (const int*)  d_in[5];
    const float* en  = (const float*)d_in[6];
    float* out = (float*)d_out;

    hist_kernel<<<(EE + 255) / 256, 256>>>(ei);
    scan_block_kernel<<<SCAN_NBLK, SCAN_B>>>();
    scan_sums_kernel<<<1, 32>>>();
    finalize_scan_kernel<<<(NN + 255) / 256, 256>>>();
    permute_kernel<<<(EE + 255) / 256, 256>>>(ei, en);

    const int smem_bytes = (CC * CC + CC) * (int)sizeof(u64)
                         + 2 * RT * CC * (int)sizeof(float);   // 197,632 B
    static int smem_set = 0;
    if (!smem_set) {
        cudaFuncSetAttribute(fused_kernel,
                             cudaFuncAttributeMaxDynamicSharedMemorySize, smem_bytes);
        smem_set = 1;
    }
    fused_kernel<<<GBLK, THREADS, smem_bytes>>>(emb, lw, lb, sw, sb, out);
}

// round 7
// speedup vs baseline: 1.5165x; 1.0685x over previous
#include <cuda_runtime.h>
#include <cuda_bf16.h>
#include <math.h>

typedef unsigned long long u64;
typedef unsigned int u32;

#define NN 100000
#define CC 128
#define EE 600000
#define EPSV 1e-10f

#define RT 64                           // rows per tile (M)
#define NTILES ((NN + RT - 1) / RT)     // 1563
#define GBLK 148
#define THREADS 512                     // 8 compute + 8 producer warps

#define SCAN_B 1024
#define SCAN_NBLK ((NN + SCAN_B - 1) / SCAN_B)

// ---------------------------------------------------------------------------
// Device scratch
// ---------------------------------------------------------------------------
__device__ int g_cnt[NN];
__device__ int g_scan[NN];
__device__ int g_rowstart[NN];
__device__ int g_cursor[NN];
__device__ int g_bsums[SCAN_NBLK];
__device__ u64 g_edges[EE];             // (norm:f32 << 32 | src:u32)

// ---------------------------------------------------------------------------
// SMEM layout (bytes). Row stride 256B (128 bf16), 16B-chunk XOR swizzle.
// ---------------------------------------------------------------------------
#define SM_BHI   0                       // 256 x 128 bf16 = 64K
#define SM_BLO   65536                   // 64K
#define SM_A0HI  131072                  // 64 x 128 bf16 = 16K
#define SM_A0LO  147456
#define SM_A1HI  163840
#define SM_A1LO  180224
#define SM_BIAS  196608                  // 256 f32 = 1K
#define SM_TOTAL 197632

// swizzled byte offset of (row, k) in a 256B-stride bf16 tile (k mult of 8 for
// ldmatrix rows; general k handled by caller)
__device__ __forceinline__ u32 tswz(int row, int k) {
    return (u32)row * 256u + ((((u32)k >> 3) ^ ((u32)row & 7u)) << 4)
         + ((u32)k & 7u) * 2u;
}

__device__ __forceinline__ u32 smem_u32(const void* p) {
    u32 a;
    asm("{ .reg .u64 t; cvta.to.shared.u64 t, %1; cvt.u32.u64 %0, t; }"
        : "=r"(a) : "l"(p));
    return a;
}

__device__ __forceinline__ void ldsm_x4(u32 addr, u32& r0, u32& r1, u32& r2, u32& r3) {
    asm volatile("ldmatrix.sync.aligned.m8n8.x4.shared.b16 {%0,%1,%2,%3}, [%4];"
                 : "=r"(r0), "=r"(r1), "=r"(r2), "=r"(r3) : "r"(addr));
}

__device__ __forceinline__ void mma_bf16(float* d, const u32* a, u32 b0, u32 b1) {
    asm volatile(
        "mma.sync.aligned.m16n8k16.row.col.f32.bf16.bf16.f32 "
        "{%0,%1,%2,%3}, {%4,%5,%6,%7}, {%8,%9}, {%0,%1,%2,%3};"
        : "+f"(d[0]), "+f"(d[1]), "+f"(d[2]), "+f"(d[3])
        : "r"(a[0]), "r"(a[1]), "r"(a[2]), "r"(a[3]), "r"(b0), "r"(b1));
}

// bf16 2-term split of float4 -> packed 4xbf16 hi/lo (two 8B words)
__device__ __forceinline__ void split4(float4 a, u64& hi, u64& lo) {
    __nv_bfloat16 h0 = __float2bfloat16_rn(a.x);
    __nv_bfloat16 h1 = __float2bfloat16_rn(a.y);
    __nv_bfloat16 h2 = __float2bfloat16_rn(a.z);
    __nv_bfloat16 h3 = __float2bfloat16_rn(a.w);
    __nv_bfloat16 l0 = __float2bfloat16_rn(a.x - __bfloat162float(h0));
    __nv_bfloat16 l1 = __float2bfloat16_rn(a.y - __bfloat162float(h1));
    __nv_bfloat16 l2 = __float2bfloat16_rn(a.z - __bfloat162float(h2));
    __nv_bfloat16 l3 = __float2bfloat16_rn(a.w - __bfloat162float(h3));
    u32 hA = (u32)__bfloat16_as_ushort(h0) | ((u32)__bfloat16_as_ushort(h1) << 16);
    u32 hB = (u32)__bfloat16_as_ushort(h2) | ((u32)__bfloat16_as_ushort(h3) << 16);
    u32 lA = (u32)__bfloat16_as_ushort(l0) | ((u32)__bfloat16_as_ushort(l1) << 16);
    u32 lB = (u32)__bfloat16_as_ushort(l2) | ((u32)__bfloat16_as_ushort(l3) << 16);
    hi = (u64)hA | ((u64)hB << 32);
    lo = (u64)lA | ((u64)lB << 32);
}

// ---------------------------------------------------------------------------
// CSR build (proven pipeline, unchanged)
// ---------------------------------------------------------------------------
__global__ void hist_kernel(const int* __restrict__ ei) {
    const int e = blockIdx.x * blockDim.x + threadIdx.x;
    if (e < EE) atomicAdd(&g_cnt[__ldg(ei + EE + e)], 1);
}

__global__ __launch_bounds__(SCAN_B)
void scan_block_kernel() {
    __shared__ int wsum[32];
    const int tid = threadIdx.x, gi = blockIdx.x * SCAN_B + tid;
    const int lane = tid & 31, wid = tid >> 5;
    int v = (gi < NN) ? g_cnt[gi] : 0;
    int s = v;
#pragma unroll
    for (int d = 1; d < 32; d <<= 1) {
        int t = __shfl_up_sync(0xffffffffu, s, d);
        if (lane >= d) s += t;
    }
    if (lane == 31) wsum[wid] = s;
    __syncthreads();
    if (wid == 0) {
        int wv = wsum[lane];
        int ws = wv;
#pragma unroll
        for (int d = 1; d < 32; d <<= 1) {
            int t = __shfl_up_sync(0xffffffffu, ws, d);
            if (lane >= d) ws += t;
        }
        wsum[lane] = ws - wv;
    }
    __syncthreads();
    const int incl = s + wsum[wid];
    if (gi < NN) g_scan[gi] = incl;
    if (tid == SCAN_B - 1) g_bsums[blockIdx.x] = incl;
}

__global__ void scan_sums_kernel() {
    const int lane = threadIdx.x & 31;
    const int base = lane * 4;
    int v[4], tot = 0;
#pragma unroll
    for (int j = 0; j < 4; j++) {
        const int idx = base + j;
        v[j] = (idx < SCAN_NBLK) ? g_bsums[idx] : 0;
        tot += v[j];
    }
    int s = tot;
#pragma unroll
    for (int d = 1; d < 32; d <<= 1) {
        int t = __shfl_up_sync(0xffffffffu, s, d);
        if (lane >= d) s += t;
    }
    int run = s - tot;
#pragma unroll
    for (int j = 0; j < 4; j++) {
        const int idx = base + j;
        if (idx < SCAN_NBLK) g_bsums[idx] = run;
        run += v[j];
    }
}

__global__ void finalize_scan_kernel() {
    const int i = blockIdx.x * blockDim.x + threadIdx.x;
    if (i < NN) {
        const int rs = g_scan[i] - g_cnt[i] + g_bsums[i / SCAN_B];
        g_rowstart[i] = rs;
        g_cursor[i]   = rs;
    }
}

__global__ void permute_kernel(const int* __restrict__ ei,
                               const float* __restrict__ en) {
    const int e = blockIdx.x * blockDim.x + threadIdx.x;
    if (e >= EE) return;
    const int   s = __ldg(ei + e);
    const int   t = __ldg(ei + EE + e);
    const float n = __ldg(en + e);
    const int   p = atomicAdd(&g_cursor[t], 1);
    g_edges[p] = ((u64)__float_as_uint(n) << 32) | (u32)s;
}

// ---------------------------------------------------------------------------
// Producer gather: 8 warps x 8 rows = 64-row tile; fp32 accumulate, bf16
// split, swizzled 8B stores into A hi/lo buffers.
// ---------------------------------------------------------------------------
__device__ __forceinline__ void gather_tile(char* smem, u32 a_hi, u32 a_lo,
                                            int tile, const float* __restrict__ emb,
                                            int pw, int lane) {
    const int rbase = tile * RT + pw * 8;
#pragma unroll 1
    for (int r = 0; r < 8; r++) {
        const int row = rbase + r;
        float4 a = make_float4(0.f, 0.f, 0.f, 0.f);
        if (row < NN) {
            const int beg = __ldg(&g_rowstart[row]);
            const int cnt = __ldg(&g_cnt[row]);
            int i = 0;
            for (; i + 3 < cnt; i += 4) {
                const u64 r0 = __ldg(&g_edges[beg + i]);
                const u64 r1 = __ldg(&g_edges[beg + i + 1]);
                const u64 r2 = __ldg(&g_edges[beg + i + 2]);
                const u64 r3 = __ldg(&g_edges[beg + i + 3]);
                const float4 v0 = *reinterpret_cast<const float4*>(emb + (size_t)(u32)r0 * CC + lane * 4);
                const float4 v1 = *reinterpret_cast<const float4*>(emb + (size_t)(u32)r1 * CC + lane * 4);
                const float4 v2 = *reinterpret_cast<const float4*>(emb + (size_t)(u32)r2 * CC + lane * 4);
                const float4 v3 = *reinterpret_cast<const float4*>(emb + (size_t)(u32)r3 * CC + lane * 4);
                const float n0 = __uint_as_float((u32)(r0 >> 32));
                const float n1 = __uint_as_float((u32)(r1 >> 32));
                const float n2 = __uint_as_float((u32)(r2 >> 32));
                const float n3 = __uint_as_float((u32)(r3 >> 32));
                a.x += v0.x * n0; a.y += v0.y * n0; a.z += v0.z * n0; a.w += v0.w * n0;
                a.x += v1.x * n1; a.y += v1.y * n1; a.z += v1.z * n1; a.w += v1.w * n1;
                a.x += v2.x * n2; a.y += v2.y * n2; a.z += v2.z * n2; a.w += v2.w * n2;
                a.x += v3.x * n3; a.y += v3.y * n3; a.z += v3.z * n3; a.w += v3.w * n3;
            }
            for (; i < cnt; i++) {
                const u64 r0 = __ldg(&g_edges[beg + i]);
                const float4 v0 = *reinterpret_cast<const float4*>(emb + (size_t)(u32)r0 * CC + lane * 4);
                const float n0 = __uint_as_float((u32)(r0 >> 32));
                a.x += v0.x * n0; a.y += v0.y * n0; a.z += v0.z * n0; a.w += v0.w * n0;
            }
            if (lane == 0) g_cnt[row] = 0;   // self-clean for next invocation
        }
        u64 hi, lo;
        split4(a, hi, lo);
        const int rloc = pw * 8 + r;
        const u32 off = tswz(rloc, lane * 4);
        *reinterpret_cast<u64*>(smem + a_hi + off) = hi;
        *reinterpret_cast<u64*>(smem + a_lo + off) = lo;
    }
}

// ---------------------------------------------------------------------------
// FUSED persistent kernel: producer gather || mma.sync bf16 3-pass dual GEMM
// with bias + softplus epilogue (direct global stores).
// ---------------------------------------------------------------------------
__global__ __launch_bounds__(THREADS, 1)
void fused_kernel(const float* __restrict__ emb,
                  const float* __restrict__ lw, const float* __restrict__ lb,
                  const float* __restrict__ sw, const float* __restrict__ sb,
                  float* __restrict__ out) {
    extern __shared__ char smem[];
    const int tid  = threadIdx.x;
    const int w    = tid >> 5;
    const int lane = tid & 31;
    const u32 sbase = smem_u32(smem);

    // ---- weights -> bf16 hi/lo swizzled tiles; bias -> smem ----
    for (int idx = tid; idx < 256 * CC / 4; idx += THREADS) {
        const int jc = idx >> 5;            // combined output channel 0..255
        const int k4 = (idx & 31) * 4;
        const float* src = (jc < CC) ? (lw + jc * CC + k4) : (sw + (jc - CC) * CC + k4);
        float4 v = *reinterpret_cast<const float4*>(src);
        u64 hi, lo;
        split4(v, hi, lo);
        const u32 off = tswz(jc, k4);
        *reinterpret_cast<u64*>(smem + SM_BHI + off) = hi;
        *reinterpret_cast<u64*>(smem + SM_BLO + off) = lo;
    }
    if (tid < 256)
        reinterpret_cast<float*>(smem + SM_BIAS)[tid] =
            (tid < 128) ? __ldg(lb + tid) : __ldg(sb + tid - 128);

    // ---- prologue: producers fill buffer 0 ----
    if (w >= 8) gather_tile(smem, SM_A0HI, SM_A0LO, blockIdx.x, emb, w - 8, lane);
    __syncthreads();

    // compute warp geometry: mi = row half (m32), nj = col quarter (n64)
    const int mi = w & 1;
    const int nj = w >> 1;
    // per-lane ldmatrix address components
    const int arow0 = mi * 32 + (lane & 15);          // + t*16
    const int ka    = (lane & 16) ? 8 : 0;
    const int bg    = lane >> 3;
    const int brow0 = nj * 64 + ((bg >> 1) << 3) + (lane & 7);   // + nb16*16
    const int kb    = (bg & 1) ? 8 : 0;
    const float* bias = reinterpret_cast<const float*>(smem + SM_BIAS);

    int buf = 0;
    for (int tile = blockIdx.x; tile < NTILES; tile += GBLK) {
        const u32 aHI = buf ? SM_A1HI : SM_A0HI;
        const u32 aLO = buf ? SM_A1LO : SM_A0LO;
        const u32 nHI = buf ? SM_A0HI : SM_A1HI;
        const u32 nLO = buf ? SM_A0LO : SM_A1LO;

        if (w >= 8) {
            const int t2 = tile + GBLK;
            if (t2 < NTILES) gather_tile(smem, nHI, nLO, t2, emb, w - 8, lane);
        } else {
            float acc[2][8][4];
#pragma unroll
            for (int t = 0; t < 2; t++)
#pragma unroll
                for (int nb = 0; nb < 8; nb++)
#pragma unroll
                    for (int q = 0; q < 4; q++) acc[t][nb][q] = 0.f;

#pragma unroll 1
            for (int kk = 0; kk < 8; kk++) {
                const int k0 = kk * 16;
                u32 ah[2][4], al[2][4];
#pragma unroll
                for (int t = 0; t < 2; t++) {
                    const int ar = arow0 + t * 16;
                    const u32 aoff = tswz(ar, k0 + ka);
                    ldsm_x4(sbase + aHI + aoff, ah[t][0], ah[t][1], ah[t][2], ah[t][3]);
                    ldsm_x4(sbase + aLO + aoff, al[t][0], al[t][1], al[t][2], al[t][3]);
                }
#pragma unroll
                for (int nb16 = 0; nb16 < 4; nb16++) {
                    const int br = brow0 + nb16 * 16;
                    const u32 boff = tswz(br, k0 + kb);
                    u32 bh0, bh1, bh2, bh3, bl0, bl1, bl2, bl3;
                    ldsm_x4(sbase + SM_BHI + boff, bh0, bh1, bh2, bh3);
                    ldsm_x4(sbase + SM_BLO + boff, bl0, bl1, bl2, bl3);
#pragma unroll
                    for (int t = 0; t < 2; t++) {
                        mma_bf16(acc[t][nb16 * 2    ], ah[t], bh0, bh1);
                        mma_bf16(acc[t][nb16 * 2 + 1], ah[t], bh2, bh3);
                        mma_bf16(acc[t][nb16 * 2    ], al[t], bh0, bh1);
                        mma_bf16(acc[t][nb16 * 2 + 1], al[t], bh2, bh3);
                        mma_bf16(acc[t][nb16 * 2    ], ah[t], bl0, bl1);
                        mma_bf16(acc[t][nb16 * 2 + 1], ah[t], bl2, bl3);
                    }
                }
            }

            // ---- epilogue: bias (+softplus for std cols>=128), direct STG ----
            const bool is_std = (nj >= 2);
            float* obase = is_std ? (out + (size_t)NN * CC - 128) : out;
#pragma unroll
            for (int t = 0; t < 2; t++) {
#pragma unroll
                for (int nb = 0; nb < 8; nb++) {
                    const int colc = nj * 64 + nb * 8 + (lane & 3) * 2;
                    const float b0 = bias[colc], b1 = bias[colc + 1];
#pragma unroll
                    for (int h = 0; h < 2; h++) {
                        const int row = tile * RT + mi * 32 + t * 16 + (lane >> 2) + h * 8;
                        if (row >= NN) continue;
                        float x0 = acc[t][nb][h * 2]     + b0;
                        float x1 = acc[t][nb][h * 2 + 1] + b1;
                        if (is_std) {
                            x0 = fmaxf(x0, 0.f) + log1pf(__expf(-fabsf(x0))) + EPSV;
                            x1 = fmaxf(x1, 0.f) + log1pf(__expf(-fabsf(x1))) + EPSV;
                        }
                        *reinterpret_cast<float2*>(obase + (size_t)row * CC + colc)
                            = make_float2(x0, x1);
                    }
                }
            }
        }
        __syncthreads();
        buf ^= 1;
    }
}

// ---------------------------------------------------------------------------
// Launch. Inputs: emb, loc_w, loc_b, std_w, std_b, edge_index, edge_norm
// ---------------------------------------------------------------------------
extern "C" void kernel_launch(void* const* d_in, const int* in_sizes, int n_in,
                              void* d_out, int out_size) {
    const float* emb = (const float*)d_in[0];
    const float* lw  = (const float*)d_in[1];
    const float* lb  = (const float*)d_in[2];
    const float* sw  = (const float*)d_in[3];
    const float* sb  = (const float*)d_in[4];
    const int*   ei  = (const int*)  d_in[5];
    const float* en  = (const float*)d_in[6];
    float* out = (float*)d_out;

    hist_kernel<<<(EE + 255) / 256, 256>>>(ei);
    scan_block_kernel<<<SCAN_NBLK, SCAN_B>>>();
    scan_sums_kernel<<<1, 32>>>();
    finalize_scan_kernel<<<(NN + 255) / 256, 256>>>();
    permute_kernel<<<(EE + 255) / 256, 256>>>(ei, en);

    static int smem_set = 0;
    if (!smem_set) {
        cudaFuncSetAttribute(fused_kernel,
                             cudaFuncAttributeMaxDynamicSharedMemorySize, SM_TOTAL);
        smem_set = 1;
    }
    fused_kernel<<<GBLK, THREADS, SM_TOTAL>>>(emb, lw, lb, sw, sb, out);
}

// round 8
// speedup vs baseline: 2.2351x; 1.4739x over previous
#include <cuda_runtime.h>
#include <cuda_bf16.h>
#include <math.h>

typedef unsigned long long u64;
typedef unsigned int u32;

#define NN 100000
#define CC 128
#define EE 600000
#define EPSV 1e-10f

#define RT 128                          // rows per GEMM tile
#define NTILES ((NN + RT - 1) / RT)     // 782
#define GBLK 148
#define GTHREADS 512                    // 16 MMA warps

#define SCAN_B 1024
#define SCAN_NBLK ((NN + SCAN_B - 1) / SCAN_B)

// ---------------------------------------------------------------------------
// Device scratch
// ---------------------------------------------------------------------------
__device__ float g_ptr[(size_t)NN * CC]; // segment-sum result (51.2 MB)
__device__ int g_cnt[NN];
__device__ int g_scan[NN];
__device__ int g_rowstart[NN];
__device__ int g_cursor[NN];
__device__ int g_bsums[SCAN_NBLK];
__device__ u64 g_edges[EE];              // (norm:f32 << 32 | src:u32)

// ---------------------------------------------------------------------------
// SMEM layout for GEMM (bytes). Row stride 256B (128 bf16), 16B XOR swizzle.
// ---------------------------------------------------------------------------
#define SM_BHI   0                       // 256 x 128 bf16 = 64K
#define SM_BLO   65536
#define SM_AHI   131072                  // 128 x 128 bf16 = 32K
#define SM_ALO   163840
#define SM_BIAS  196608                  // 256 f32 = 1K
#define SM_TOTAL 197632

__device__ __forceinline__ u32 tswz(int row, int k) {
    return (u32)row * 256u + ((((u32)k >> 3) ^ ((u32)row & 7u)) << 4)
         + ((u32)k & 7u) * 2u;
}
__device__ __forceinline__ u32 smem_u32(const void* p) {
    u32 a;
    asm("{ .reg .u64 t; cvta.to.shared.u64 t, %1; cvt.u32.u64 %0, t; }"
        : "=r"(a) : "l"(p));
    return a;
}
__device__ __forceinline__ void ldsm_x4(u32 addr, u32& r0, u32& r1, u32& r2, u32& r3) {
    asm volatile("ldmatrix.sync.aligned.m8n8.x4.shared.b16 {%0,%1,%2,%3}, [%4];"
                 : "=r"(r0), "=r"(r1), "=r"(r2), "=r"(r3) : "r"(addr));
}
__device__ __forceinline__ void mma_bf16(float* d, const u32* a, u32 b0, u32 b1) {
    asm volatile(
        "mma.sync.aligned.m16n8k16.row.col.f32.bf16.bf16.f32 "
        "{%0,%1,%2,%3}, {%4,%5,%6,%7}, {%8,%9}, {%0,%1,%2,%3};"
        : "+f"(d[0]), "+f"(d[1]), "+f"(d[2]), "+f"(d[3])
        : "r"(a[0]), "r"(a[1]), "r"(a[2]), "r"(a[3]), "r"(b0), "r"(b1));
}
__device__ __forceinline__ void split4(float4 a, u64& hi, u64& lo) {
    __nv_bfloat16 h0 = __float2bfloat16_rn(a.x);
    __nv_bfloat16 h1 = __float2bfloat16_rn(a.y);
    __nv_bfloat16 h2 = __float2bfloat16_rn(a.z);
    __nv_bfloat16 h3 = __float2bfloat16_rn(a.w);
    __nv_bfloat16 l0 = __float2bfloat16_rn(a.x - __bfloat162float(h0));
    __nv_bfloat16 l1 = __float2bfloat16_rn(a.y - __bfloat162float(h1));
    __nv_bfloat16 l2 = __float2bfloat16_rn(a.z - __bfloat162float(h2));
    __nv_bfloat16 l3 = __float2bfloat16_rn(a.w - __bfloat162float(h3));
    u32 hA = (u32)__bfloat16_as_ushort(h0) | ((u32)__bfloat16_as_ushort(h1) << 16);
    u32 hB = (u32)__bfloat16_as_ushort(h2) | ((u32)__bfloat16_as_ushort(h3) << 16);
    u32 lA = (u32)__bfloat16_as_ushort(l0) | ((u32)__bfloat16_as_ushort(l1) << 16);
    u32 lB = (u32)__bfloat16_as_ushort(l2) | ((u32)__bfloat16_as_ushort(l3) << 16);
    hi = (u64)hA | ((u64)hB << 32);
    lo = (u64)lA | ((u64)lB << 32);
}

// ---------------------------------------------------------------------------
// CSR build (proven, unchanged)
// ---------------------------------------------------------------------------
__global__ void hist_kernel(const int* __restrict__ ei) {
    const int e = blockIdx.x * blockDim.x + threadIdx.x;
    if (e < EE) atomicAdd(&g_cnt[__ldg(ei + EE + e)], 1);
}

__global__ __launch_bounds__(SCAN_B)
void scan_block_kernel() {
    __shared__ int wsum[32];
    const int tid = threadIdx.x, gi = blockIdx.x * SCAN_B + tid;
    const int lane = tid & 31, wid = tid >> 5;
    int v = (gi < NN) ? g_cnt[gi] : 0;
    int s = v;
#pragma unroll
    for (int d = 1; d < 32; d <<= 1) {
        int t = __shfl_up_sync(0xffffffffu, s, d);
        if (lane >= d) s += t;
    }
    if (lane == 31) wsum[wid] = s;
    __syncthreads();
    if (wid == 0) {
        int wv = wsum[lane];
        int ws = wv;
#pragma unroll
        for (int d = 1; d < 32; d <<= 1) {
            int t = __shfl_up_sync(0xffffffffu, ws, d);
            if (lane >= d) ws += t;
        }
        wsum[lane] = ws - wv;
    }
    __syncthreads();
    const int incl = s + wsum[wid];
    if (gi < NN) g_scan[gi] = incl;
    if (tid == SCAN_B - 1) g_bsums[blockIdx.x] = incl;
}

__global__ void scan_sums_kernel() {
    const int lane = threadIdx.x & 31;
    const int base = lane * 4;
    int v[4], tot = 0;
#pragma unroll
    for (int j = 0; j < 4; j++) {
        const int idx = base + j;
        v[j] = (idx < SCAN_NBLK) ? g_bsums[idx] : 0;
        tot += v[j];
    }
    int s = tot;
#pragma unroll
    for (int d = 1; d < 32; d <<= 1) {
        int t = __shfl_up_sync(0xffffffffu, s, d);
        if (lane >= d) s += t;
    }
    int run = s - tot;
#pragma unroll
    for (int j = 0; j < 4; j++) {
        const int idx = base + j;
        if (idx < SCAN_NBLK) g_bsums[idx] = run;
        run += v[j];
    }
}

__global__ void finalize_scan_kernel() {
    const int i = blockIdx.x * blockDim.x + threadIdx.x;
    if (i < NN) {
        const int rs = g_scan[i] - g_cnt[i] + g_bsums[i / SCAN_B];
        g_rowstart[i] = rs;
        g_cursor[i]   = rs;
    }
}

__global__ void permute_kernel(const int* __restrict__ ei,
                               const float* __restrict__ en) {
    const int e = blockIdx.x * blockDim.x + threadIdx.x;
    if (e >= EE) return;
    const int   s = __ldg(ei + e);
    const int   t = __ldg(ei + EE + e);
    const float n = __ldg(en + e);
    const int   p = atomicAdd(&g_cursor[t], 1);
    g_edges[p] = ((u64)__float_as_uint(n) << 32) | (u32)s;
}

// ---------------------------------------------------------------------------
// Aggregate: one warp per node, FULL occupancy (100k warps). Gather emb rows
// of contiguous CSR edges, accumulate in registers, one float4 store.
// Self-cleans g_cnt for graph replay.
// ---------------------------------------------------------------------------
__global__ __launch_bounds__(256)
void aggregate_kernel(const float* __restrict__ emb) {
    const int node = (blockIdx.x * blockDim.x + threadIdx.x) >> 5;
    if (node >= NN) return;
    const int lane = threadIdx.x & 31;

    const int beg = __ldg(&g_rowstart[node]);
    const int cnt = __ldg(&g_cnt[node]);

    float4 a = make_float4(0.f, 0.f, 0.f, 0.f);
    int i = 0;
    for (; i + 3 < cnt; i += 4) {
        const u64 r0 = __ldg(&g_edges[beg + i]);
        const u64 r1 = __ldg(&g_edges[beg + i + 1]);
        const u64 r2 = __ldg(&g_edges[beg + i + 2]);
        const u64 r3 = __ldg(&g_edges[beg + i + 3]);
        const float4 v0 = *reinterpret_cast<const float4*>(emb + (size_t)(u32)r0 * CC + lane * 4);
        const float4 v1 = *reinterpret_cast<const float4*>(emb + (size_t)(u32)r1 * CC + lane * 4);
        const float4 v2 = *reinterpret_cast<const float4*>(emb + (size_t)(u32)r2 * CC + lane * 4);
        const float4 v3 = *reinterpret_cast<const float4*>(emb + (size_t)(u32)r3 * CC + lane * 4);
        const float n0 = __uint_as_float((u32)(r0 >> 32));
        const float n1 = __uint_as_float((u32)(r1 >> 32));
        const float n2 = __uint_as_float((u32)(r2 >> 32));
        const float n3 = __uint_as_float((u32)(r3 >> 32));
        a.x += v0.x * n0; a.y += v0.y * n0; a.z += v0.z * n0; a.w += v0.w * n0;
        a.x += v1.x * n1; a.y += v1.y * n1; a.z += v1.z * n1; a.w += v1.w * n1;
        a.x += v2.x * n2; a.y += v2.y * n2; a.z += v2.z * n2; a.w += v2.w * n2;
        a.x += v3.x * n3; a.y += v3.y * n3; a.z += v3.z * n3; a.w += v3.w * n3;
    }
    for (; i < cnt; i++) {
        const u64 r0 = __ldg(&g_edges[beg + i]);
        const float4 v0 = *reinterpret_cast<const float4*>(emb + (size_t)(u32)r0 * CC + lane * 4);
        const float n0 = __uint_as_float((u32)(r0 >> 32));
        a.x += v0.x * n0; a.y += v0.y * n0; a.z += v0.z * n0; a.w += v0.w * n0;
    }
    if (lane == 0) g_cnt[node] = 0;   // self-clean for next invocation
    *reinterpret_cast<float4*>(g_ptr + (size_t)node * CC + lane * 4) = a;
}

// ---------------------------------------------------------------------------
// Persistent MMA GEMM: 16 warps, RT=128 tiles. Streams g_ptr (coalesced),
// bf16 3-pass split (Ah*Bh + Al*Bh + Ah*Bl), bias + softplus epilogue.
// Warp w: rows mi*32 (mi=w&3), cols nj*64 (nj=w>>2).
// ---------------------------------------------------------------------------
__global__ __launch_bounds__(GTHREADS, 1)
void gemm_kernel(const float* __restrict__ lw, const float* __restrict__ lb,
                 const float* __restrict__ sw, const float* __restrict__ sb,
                 float* __restrict__ out) {
    extern __shared__ char smem[];
    const int tid  = threadIdx.x;
    const int w    = tid >> 5;
    const int lane = tid & 31;
    const u32 sbase = smem_u32(smem);

    // ---- weights -> bf16 hi/lo swizzled tiles; bias -> smem ----
    for (int idx = tid; idx < 256 * CC / 4; idx += GTHREADS) {
        const int jc = idx >> 5;
        const int k4 = (idx & 31) * 4;
        const float* src = (jc < CC) ? (lw + jc * CC + k4) : (sw + (jc - CC) * CC + k4);
        float4 v = *reinterpret_cast<const float4*>(src);
        u64 hi, lo;
        split4(v, hi, lo);
        const u32 off = tswz(jc, k4);
        *reinterpret_cast<u64*>(smem + SM_BHI + off) = hi;
        *reinterpret_cast<u64*>(smem + SM_BLO + off) = lo;
    }
    if (tid < 256)
        reinterpret_cast<float*>(smem + SM_BIAS)[tid] =
            (tid < 128) ? __ldg(lb + tid) : __ldg(sb + tid - 128);

    const int mi = w & 3;
    const int nj = w >> 2;
    const int arow0 = mi * 32 + (lane & 15);
    const int ka    = (lane & 16) ? 8 : 0;
    const int bg    = lane >> 3;
    const int brow0 = nj * 64 + ((bg >> 1) << 3) + (lane & 7);
    const int kb    = (bg & 1) ? 8 : 0;
    const float* bias = reinterpret_cast<const float*>(smem + SM_BIAS);
    const bool is_std = (nj >= 2);
    float* obase = is_std ? (out + (size_t)NN * CC - 128) : out;

    __syncthreads();

    for (int tile = blockIdx.x; tile < NTILES; tile += GBLK) {
        const int row0 = tile * RT;

        // ---- stream A tile from g_ptr (coalesced), split, store swizzled ----
        {
            float4 v[8];
#pragma unroll
            for (int j = 0; j < 8; j++) {
                const int idx = tid + j * GTHREADS;      // 0..4095
                const int row = idx >> 5;
                const int k4  = (idx & 31) * 4;
                v[j] = (row0 + row < NN)
                     ? *reinterpret_cast<const float4*>(g_ptr + (size_t)(row0 + row) * CC + k4)
                     : make_float4(0.f, 0.f, 0.f, 0.f);
            }
#pragma unroll
            for (int j = 0; j < 8; j++) {
                const int idx = tid + j * GTHREADS;
                const int row = idx >> 5;
                const int k4  = (idx & 31) * 4;
                u64 hi, lo;
                split4(v[j], hi, lo);
                const u32 off = tswz(row, k4);
                *reinterpret_cast<u64*>(smem + SM_AHI + off) = hi;
                *reinterpret_cast<u64*>(smem + SM_ALO + off) = lo;
            }
        }
        __syncthreads();

        float acc[2][8][4];
#pragma unroll
        for (int t = 0; t < 2; t++)
#pragma unroll
            for (int nb = 0; nb < 8; nb++)
#pragma unroll
                for (int q = 0; q < 4; q++) acc[t][nb][q] = 0.f;

#pragma unroll 1
        for (int kk = 0; kk < 8; kk++) {
            const int k0 = kk * 16;
            u32 ah[2][4], al[2][4];
#pragma unroll
            for (int t = 0; t < 2; t++) {
                const int ar = arow0 + t * 16;
                const u32 aoff = tswz(ar, k0 + ka);
                ldsm_x4(sbase + SM_AHI + aoff, ah[t][0], ah[t][1], ah[t][2], ah[t][3]);
                ldsm_x4(sbase + SM_ALO + aoff, al[t][0], al[t][1], al[t][2], al[t][3]);
            }
#pragma unroll
            for (int nb16 = 0; nb16 < 4; nb16++) {
                const int br = brow0 + nb16 * 16;
                const u32 boff = tswz(br, k0 + kb);
                u32 bh0, bh1, bh2, bh3, bl0, bl1, bl2, bl3;
                ldsm_x4(sbase + SM_BHI + boff, bh0, bh1, bh2, bh3);
                ldsm_x4(sbase + SM_BLO + boff, bl0, bl1, bl2, bl3);
#pragma unroll
                for (int t = 0; t < 2; t++) {
                    mma_bf16(acc[t][nb16 * 2    ], ah[t], bh0, bh1);
                    mma_bf16(acc[t][nb16 * 2 + 1], ah[t], bh2, bh3);
                    mma_bf16(acc[t][nb16 * 2    ], al[t], bh0, bh1);
                    mma_bf16(acc[t][nb16 * 2 + 1], al[t], bh2, bh3);
                    mma_bf16(acc[t][nb16 * 2    ], ah[t], bl0, bl1);
                    mma_bf16(acc[t][nb16 * 2 + 1], ah[t], bl2, bl3);
                }
            }
        }

        // ---- epilogue: bias (+softplus), direct float2 stores ----
#pragma unroll
        for (int t = 0; t < 2; t++) {
#pragma unroll
            for (int nb = 0; nb < 8; nb++) {
                const int colc = nj * 64 + nb * 8 + (lane & 3) * 2;
                const float b0 = bias[colc], b1 = bias[colc + 1];
#pragma unroll
                for (int h = 0; h < 2; h++) {
                    const int row = row0 + mi * 32 + t * 16 + (lane >> 2) + h * 8;
                    if (row >= NN) continue;
                    float x0 = acc[t][nb][h * 2]     + b0;
                    float x1 = acc[t][nb][h * 2 + 1] + b1;
                    if (is_std) {
                        x0 = fmaxf(x0, 0.f) + log1pf(__expf(-fabsf(x0))) + EPSV;
                        x1 = fmaxf(x1, 0.f) + log1pf(__expf(-fabsf(x1))) + EPSV;
                    }
                    *reinterpret_cast<float2*>(obase + (size_t)row * CC + colc)
                        = make_float2(x0, x1);
                }
            }
        }
        __syncthreads();
    }
}

// ---------------------------------------------------------------------------
// Launch. Inputs: emb, loc_w, loc_b, std_w, std_b, edge_index, edge_norm
// ---------------------------------------------------------------------------
extern "C" void kernel_launch(void* const* d_in, const int* in_sizes, int n_in,
                              void* d_out, int out_size) {
    const float* emb = (const float*)d_in[0];
    const float* lw  = (const float*)d_in[1];
    const float* lb  = (const float*)d_in[2];
    const float* sw  = (const float*)d_in[3];
    const float* sb  = (const float*)d_in[4];
    const int*   ei  = (const int*)  d_in[5];
    const float* en  = (const float*)d_in[6];
    float* out = (float*)d_out;

    hist_kernel<<<(EE + 255) / 256, 256>>>(ei);
    scan_block_kernel<<<SCAN_NBLK, SCAN_B>>>();
    scan_sums_kernel<<<1, 32>>>();
    finalize_scan_kernel<<<(NN + 255) / 256, 256>>>();
    permute_kernel<<<(EE + 255) / 256, 256>>>(ei, en);

    aggregate_kernel<<<(NN * 32 + 255) / 256, 256>>>(emb);

    static int smem_set = 0;
    if (!smem_set) {
        cudaFuncSetAttribute(gemm_kernel,
                             cudaFuncAttributeMaxDynamicSharedMemorySize, SM_TOTAL);
        smem_set = 1;
    }
    gemm_kernel<<<GBLK, GTHREADS, SM_TOTAL>>>(lw, lb, sw, sb, out);
}

// round 10
// speedup vs baseline: 2.3298x; 1.0424x over previous
#include <cuda_runtime.h>
#include <cuda_bf16.h>
#include <math.h>

typedef unsigned long long u64;
typedef unsigned int u32;

#define NN 100000
#define CC 128
#define EE 600000
#define EPSV 1e-10f

#define RT 128                          // rows per GEMM tile
#define NTILES ((NN + RT - 1) / RT)     // 782
#define NPAD (NTILES * RT)              // 100096 (zero-padded node rows)
#define GBLK 148
#define GTHREADS 512                    // 16 MMA warps

#define SCAN_B 1024
#define SCAN_NBLK ((NN + SCAN_B - 1) / SCAN_B)   // 98

// ---------------------------------------------------------------------------
// Device scratch
// ---------------------------------------------------------------------------
__device__ u64 g_ahi[(size_t)NPAD * 32]; // aggregated rows, bf16-hi packed (25.6MB)
__device__ u64 g_alo[(size_t)NPAD * 32]; // bf16-lo packed (25.6MB)
__device__ int g_cnt[NN];
__device__ int g_rowstart[NN];
__device__ int g_cursor[NN];
__device__ u64 g_look[SCAN_NBLK];        // lookback: (status<<32)|value; 1=agg,2=inc
__device__ u64 g_edges[EE];              // (norm:f32 << 32 | src:u32)

// ---------------------------------------------------------------------------
// SMEM layout for GEMM (bytes). Row stride 256B (128 bf16), 16B XOR swizzle.
// ---------------------------------------------------------------------------
#define SM_BHI   0                       // 256 x 128 bf16 = 64K
#define SM_BLO   65536
#define SM_AHI   131072                  // 128 x 128 bf16 = 32K
#define SM_ALO   163840
#define SM_BIAS  196608                  // 256 f32 = 1K
#define SM_TOTAL 197632

__device__ __forceinline__ u32 tswz(int row, int k) {
    return (u32)row * 256u + ((((u32)k >> 3) ^ ((u32)row & 7u)) << 4)
         + ((u32)k & 7u) * 2u;
}
__device__ __forceinline__ u32 smem_u32(const void* p) {
    u32 a;
    asm("{ .reg .u64 t; cvta.to.shared.u64 t, %1; cvt.u32.u64 %0, t; }"
        : "=r"(a) : "l"(p));
    return a;
}
__device__ __forceinline__ void ldsm_x4(u32 addr, u32& r0, u32& r1, u32& r2, u32& r3) {
    asm volatile("ldmatrix.sync.aligned.m8n8.x4.shared.b16 {%0,%1,%2,%3}, [%4];"
                 : "=r"(r0), "=r"(r1), "=r"(r2), "=r"(r3) : "r"(addr));
}
__device__ __forceinline__ void mma_bf16(float* d, const u32* a, u32 b0, u32 b1) {
    asm volatile(
        "mma.sync.aligned.m16n8k16.row.col.f32.bf16.bf16.f32 "
        "{%0,%1,%2,%3}, {%4,%5,%6,%7}, {%8,%9}, {%0,%1,%2,%3};"
        : "+f"(d[0]), "+f"(d[1]), "+f"(d[2]), "+f"(d[3])
        : "r"(a[0]), "r"(a[1]), "r"(a[2]), "r"(a[3]), "r"(b0), "r"(b1));
}
__device__ __forceinline__ void split4(float4 a, u64& hi, u64& lo) {
    __nv_bfloat16 h0 = __float2bfloat16_rn(a.x);
    __nv_bfloat16 h1 = __float2bfloat16_rn(a.y);
    __nv_bfloat16 h2 = __float2bfloat16_rn(a.z);
    __nv_bfloat16 h3 = __float2bfloat16_rn(a.w);
    __nv_bfloat16 l0 = __float2bfloat16_rn(a.x - __bfloat162float(h0));
    __nv_bfloat16 l1 = __float2bfloat16_rn(a.y - __bfloat162float(h1));
    __nv_bfloat16 l2 = __float2bfloat16_rn(a.z - __bfloat162float(h2));
    __nv_bfloat16 l3 = __float2bfloat16_rn(a.w - __bfloat162float(h3));
    u32 hA = (u32)__bfloat16_as_ushort(h0) | ((u32)__bfloat16_as_ushort(h1) << 16);
    u32 hB = (u32)__bfloat16_as_ushort(h2) | ((u32)__bfloat16_as_ushort(h3) << 16);
    u32 lA = (u32)__bfloat16_as_ushort(l0) | ((u32)__bfloat16_as_ushort(l1) << 16);
    u32 lB = (u32)__bfloat16_as_ushort(l2) | ((u32)__bfloat16_as_ushort(l3) << 16);
    hi = (u64)hA | ((u64)hB << 32);
    lo = (u64)lA | ((u64)lB << 32);
}
__device__ __forceinline__ int warp_sum(int v) {
#pragma unroll
    for (int d = 16; d > 0; d >>= 1) v += __shfl_xor_sync(0xffffffffu, v, d);
    return v;
}

// ---------------------------------------------------------------------------
// Kernel 1: histogram of edge targets
// ---------------------------------------------------------------------------
__global__ void hist_kernel(const int* __restrict__ ei) {
    const int e = blockIdx.x * blockDim.x + threadIdx.x;
    if (e < EE) atomicAdd(&g_cnt[__ldg(ei + EE + e)], 1);
}

// ---------------------------------------------------------------------------
// Kernel 2: single-pass decoupled-lookback scan. Writes rowstart + cursor.
// g_look starts zero (BSS on first call; reset by permute for replays).
// RACE FIX vs R9: dedicated s_total/s_prefix; publish happens after incl is
// computed and is sealed by a __syncthreads() before any consumer.
// ---------------------------------------------------------------------------
__global__ __launch_bounds__(SCAN_B)
void scan_kernel() {
    __shared__ int wsum[32];
    __shared__ int s_total;
    __shared__ int s_prefix;

    const int b    = blockIdx.x;
    const int tid  = threadIdx.x;
    const int lane = tid & 31;
    const int wid  = tid >> 5;
    const int gi   = b * SCAN_B + tid;

    const int v = (gi < NN) ? g_cnt[gi] : 0;
    int s = v;
#pragma unroll
    for (int d = 1; d < 32; d <<= 1) {
        int t = __shfl_up_sync(0xffffffffu, s, d);
        if (lane >= d) s += t;
    }
    if (lane == 31) wsum[wid] = s;
    __syncthreads();
    if (wid == 0) {
        int wv = wsum[lane];
        int ws = wv;
#pragma unroll
        for (int d = 1; d < 32; d <<= 1) {
            int t = __shfl_up_sync(0xffffffffu, ws, d);
            if (lane >= d) ws += t;
        }
        wsum[lane] = ws - wv;         // exclusive warp offsets
    }
    __syncthreads();
    const int incl = s + wsum[wid];   // block-local inclusive (all threads)

    // publish block aggregate (status 2 = inclusive for block 0)
    if (tid == SCAN_B - 1) {
        s_total = incl;
        const u64 st = (b == 0) ? 2ull : 1ull;
        *(volatile u64*)&g_look[b] = (st << 32) | (u32)incl;
    }
    __syncthreads();                  // seals s_total AND all wsum reads

    // warp 0: lookback for exclusive prefix of previous blocks
    if (b == 0) {
        if (tid == 0) s_prefix = 0;
    } else if (wid == 0) {
        int sum = 0;
        int p = b - 1;
        for (;;) {
            const int idx = p - lane;
            u64 packed = 0;
            if (idx >= 0) {
                do { packed = *(volatile u64*)&g_look[idx]; }
                while ((packed >> 32) == 0ull);
            }
            const int st  = (int)(packed >> 32);
            const int val = (int)(u32)packed;
            const u32 m = __ballot_sync(0xffffffffu, (idx >= 0) && (st == 2));
            if (m) {
                const int f = __ffs(m) - 1;        // closest inclusive block
                sum += warp_sum((lane <= f) ? val : 0);
                break;
            }
            sum += warp_sum((idx >= 0) ? val : 0);
            p -= 32;
        }
        if (lane == 0) {
            s_prefix = sum;
            *(volatile u64*)&g_look[b] = (2ull << 32) | (u32)(sum + s_total);
        }
    }
    __syncthreads();

    if (gi < NN) {
        const int rs = s_prefix + incl - v;
        g_rowstart[gi] = rs;
        g_cursor[gi]   = rs;
    }
}

// ---------------------------------------------------------------------------
// Kernel 3: permute edges into CSR order; also resets g_look for next replay.
// ---------------------------------------------------------------------------
__global__ void permute_kernel(const int* __restrict__ ei,
                               const float* __restrict__ en) {
    const int e = blockIdx.x * blockDim.x + threadIdx.x;
    if (e < SCAN_NBLK) g_look[e] = 0ull;
    if (e >= EE) return;
    const int   s = __ldg(ei + e);
    const int   t = __ldg(ei + EE + e);
    const float n = __ldg(en + e);
    const int   p = atomicAdd(&g_cursor[t], 1);
    g_edges[p] = ((u64)__float_as_uint(n) << 32) | (u32)s;
}

// ---------------------------------------------------------------------------
// Kernel 4: aggregate. One warp per node, full occupancy. Emits bf16 hi/lo
// split directly (GEMM A operand format). Self-cleans g_cnt.
// ---------------------------------------------------------------------------
__global__ __launch_bounds__(256)
void aggregate_kernel(const float* __restrict__ emb) {
    const int node = (blockIdx.x * blockDim.x + threadIdx.x) >> 5;
    if (node >= NN) return;
    const int lane = threadIdx.x & 31;

    const int beg = __ldg(&g_rowstart[node]);
    const int cnt = __ldg(&g_cnt[node]);

    float4 a = make_float4(0.f, 0.f, 0.f, 0.f);
    int i = 0;
    for (; i + 3 < cnt; i += 4) {
        const u64 r0 = __ldg(&g_edges[beg + i]);
        const u64 r1 = __ldg(&g_edges[beg + i + 1]);
        const u64 r2 = __ldg(&g_edges[beg + i + 2]);
        const u64 r3 = __ldg(&g_edges[beg + i + 3]);
        const float4 v0 = *reinterpret_cast<const float4*>(emb + (size_t)(u32)r0 * CC + lane * 4);
        const float4 v1 = *reinterpret_cast<const float4*>(emb + (size_t)(u32)r1 * CC + lane * 4);
        const float4 v2 = *reinterpret_cast<const float4*>(emb + (size_t)(u32)r2 * CC + lane * 4);
        const float4 v3 = *reinterpret_cast<const float4*>(emb + (size_t)(u32)r3 * CC + lane * 4);
        const float n0 = __uint_as_float((u32)(r0 >> 32));
        const float n1 = __uint_as_float((u32)(r1 >> 32));
        const float n2 = __uint_as_float((u32)(r2 >> 32));
        const float n3 = __uint_as_float((u32)(r3 >> 32));
        a.x += v0.x * n0; a.y += v0.y * n0; a.z += v0.z * n0; a.w += v0.w * n0;
        a.x += v1.x * n1; a.y += v1.y * n1; a.z += v1.z * n1; a.w += v1.w * n1;
        a.x += v2.x * n2; a.y += v2.y * n2; a.z += v2.z * n2; a.w += v2.w * n2;
        a.x += v3.x * n3; a.y += v3.y * n3; a.z += v3.z * n3; a.w += v3.w * n3;
    }
    for (; i < cnt; i++) {
        const u64 r0 = __ldg(&g_edges[beg + i]);
        const float4 v0 = *reinterpret_cast<const float4*>(emb + (size_t)(u32)r0 * CC + lane * 4);
        const float n0 = __uint_as_float((u32)(r0 >> 32));
        a.x += v0.x * n0; a.y += v0.y * n0; a.z += v0.z * n0; a.w += v0.w * n0;
    }
    if (lane == 0) g_cnt[node] = 0;   // self-clean for next invocation

    u64 hi, lo;
    split4(a, hi, lo);
    g_ahi[(size_t)node * 32 + lane] = hi;
    g_alo[(size_t)node * 32 + lane] = lo;
}

// ---------------------------------------------------------------------------
// Kernel 5: persistent MMA GEMM, bf16 3-pass split, bias + softplus epilogue.
// A operand arrives pre-split: A-fill is pure u64 copies (coalesced).
// ---------------------------------------------------------------------------
__global__ __launch_bounds__(GTHREADS, 1)
void gemm_kernel(const float* __restrict__ lw, const float* __restrict__ lb,
                 const float* __restrict__ sw, const float* __restrict__ sb,
                 float* __restrict__ out) {
    extern __shared__ char smem[];
    const int tid  = threadIdx.x;
    const int w    = tid >> 5;
    const int lane = tid & 31;
    const u32 sbase = smem_u32(smem);

    // ---- weights -> bf16 hi/lo swizzled tiles; bias -> smem ----
    for (int idx = tid; idx < 256 * CC / 4; idx += GTHREADS) {
        const int jc = idx >> 5;
        const int k4 = (idx & 31) * 4;
        const float* src = (jc < CC) ? (lw + jc * CC + k4) : (sw + (jc - CC) * CC + k4);
        float4 v = *reinterpret_cast<const float4*>(src);
        u64 hi, lo;
        split4(v, hi, lo);
        const u32 off = tswz(jc, k4);
        *reinterpret_cast<u64*>(smem + SM_BHI + off) = hi;
        *reinterpret_cast<u64*>(smem + SM_BLO + off) = lo;
    }
    if (tid < 256)
        reinterpret_cast<float*>(smem + SM_BIAS)[tid] =
            (tid < 128) ? __ldg(lb + tid) : __ldg(sb + tid - 128);

    const int mi = w & 3;
    const int nj = w >> 2;
    const int arow0 = mi * 32 + (lane & 15);
    const int ka    = (lane & 16) ? 8 : 0;
    const int bg    = lane >> 3;
    const int brow0 = nj * 64 + ((bg >> 1) << 3) + (lane & 7);
    const int kb    = (bg & 1) ? 8 : 0;
    const float* bias = reinterpret_cast<const float*>(smem + SM_BIAS);
    const bool is_std = (nj >= 2);
    float* obase = is_std ? (out + (size_t)NN * CC - 128) : out;

    __syncthreads();

    for (int tile = blockIdx.x; tile < NTILES; tile += GBLK) {
        const int row0 = tile * RT;

        // ---- A tile: straight u64 copies (pre-split, padded arrays) ----
        {
            u64 hv[8], lv[8];
#pragma unroll
            for (int j = 0; j < 8; j++) {
                const int idx = tid + j * GTHREADS;              // 0..4095
                const size_t g = (size_t)row0 * 32 + idx;
                hv[j] = g_ahi[g];
                lv[j] = g_alo[g];
            }
#pragma unroll
            for (int j = 0; j < 8; j++) {
                const int idx = tid + j * GTHREADS;
                const int row = idx >> 5;
                const int k4  = (idx & 31) * 4;
                const u32 off = tswz(row, k4);
                *reinterpret_cast<u64*>(smem + SM_AHI + off) = hv[j];
                *reinterpret_cast<u64*>(smem + SM_ALO + off) = lv[j];
            }
        }
        __syncthreads();

        float acc[2][8][4];
#pragma unroll
        for (int t = 0; t < 2; t++)
#pragma unroll
            for (int nb = 0; nb < 8; nb++)
#pragma unroll
                for (int q = 0; q < 4; q++) acc[t][nb][q] = 0.f;

#pragma unroll 1
        for (int kk = 0; kk < 8; kk++) {
            const int k0 = kk * 16;
            u32 ah[2][4], al[2][4];
#pragma unroll
            for (int t = 0; t < 2; t++) {
                const int ar = arow0 + t * 16;
                const u32 aoff = tswz(ar, k0 + ka);
                ldsm_x4(sbase + SM_AHI + aoff, ah[t][0], ah[t][1], ah[t][2], ah[t][3]);
                ldsm_x4(sbase + SM_ALO + aoff, al[t][0], al[t][1], al[t][2], al[t][3]);
            }
#pragma unroll
            for (int nb16 = 0; nb16 < 4; nb16++) {
                const int br = brow0 + nb16 * 16;
                const u32 boff = tswz(br, k0 + kb);
                u32 bh0, bh1, bh2, bh3, bl0, bl1, bl2, bl3;
                ldsm_x4(sbase + SM_BHI + boff, bh0, bh1, bh2, bh3);
                ldsm_x4(sbase + SM_BLO + boff, bl0, bl1, bl2, bl3);
#pragma unroll
                for (int t = 0; t < 2; t++) {
                    mma_bf16(acc[t][nb16 * 2    ], ah[t], bh0, bh1);
                    mma_bf16(acc[t][nb16 * 2 + 1], ah[t], bh2, bh3);
                    mma_bf16(acc[t][nb16 * 2    ], al[t], bh0, bh1);
                    mma_bf16(acc[t][nb16 * 2 + 1], al[t], bh2, bh3);
                    mma_bf16(acc[t][nb16 * 2    ], ah[t], bl0, bl1);
                    mma_bf16(acc[t][nb16 * 2 + 1], ah[t], bl2, bl3);
                }
            }
        }

        // ---- epilogue: bias (+softplus), direct float2 stores ----
#pragma unroll
        for (int t = 0; t < 2; t++) {
#pragma unroll
            for (int nb = 0; nb < 8; nb++) {
                const int colc = nj * 64 + nb * 8 + (lane & 3) * 2;
                const float b0 = bias[colc], b1 = bias[colc + 1];
#pragma unroll
                for (int h = 0; h < 2; h++) {
                    const int row = row0 + mi * 32 + t * 16 + (lane >> 2) + h * 8;
                    if (row >= NN) continue;
                    float x0 = acc[t][nb][h * 2]     + b0;
                    float x1 = acc[t][nb][h * 2 + 1] + b1;
                    if (is_std) {
                        x0 = fmaxf(x0, 0.f) + log1pf(__expf(-fabsf(x0))) + EPSV;
                        x1 = fmaxf(x1, 0.f) + log1pf(__expf(-fabsf(x1))) + EPSV;
                    }
                    *reinterpret_cast<float2*>(obase + (size_t)row * CC + colc)
                        = make_float2(x0, x1);
                }
            }
        }
        __syncthreads();
    }
}

// ---------------------------------------------------------------------------
// Launch. Inputs: emb, loc_w, loc_b, std_w, std_b, edge_index, edge_norm
// ---------------------------------------------------------------------------
extern "C" void kernel_launch(void* const* d_in, const int* in_sizes, int n_in,
                              void* d_out, int out_size) {
    const float* emb = (const float*)d_in[0];
    const float* lw  = (const float*)d_in[1];
    const float* lb  = (const float*)d_in[2];
    const float* sw  = (const float*)d_in[3];
    const float* sb  = (const float*)d_in[4];
    const int*   ei  = (const int*)  d_in[5];
    const float* en  = (const float*)d_in[6];
    float* out = (float*)d_out;

    hist_kernel<<<(EE + 255) / 256, 256>>>(ei);
    scan_kernel<<<SCAN_NBLK, SCAN_B>>>();
    permute_kernel<<<(EE + 255) / 256, 256>>>(ei, en);
    aggregate_kernel<<<(NN * 32 + 255) / 256, 256>>>(emb);

    static int smem_set = 0;
    if (!smem_set) {
        cudaFuncSetAttribute(gemm_kernel,
                             cudaFuncAttributeMaxDynamicSharedMemorySize, SM_TOTAL);
        smem_set = 1;
    }
    gemm_kernel<<<GBLK, GTHREADS, SM_TOTAL>>>(lw, lb, sw, sb, out);
}